// round 6
// baseline (speedup 1.0000x reference)
#include <cuda_runtime.h>
#include <cstdint>

#define BB 32
#define TT 36
#define NN 10000
#define FF 3
#define HH 10
#define RR 20

#define THREADS 640          // 20 warps; also 640 = BB*RR (phase-3 pairs)
#define GX 4                 // n-tiles
#define NCTA (GX * BB)       // 128 CTAs, single wave on 148 SMs
#define GPC 625              // float4-triples (=> 4 nodes) per CTA per row; GX*GPC*4 = NN
#define ROW4 (NN * FF / 4)   // 7500 float4 per (b,t) row
#define PAIRS_PER_CTA 5      // 640 pairs / 128 CTAs

// ---- device scratch (no allocations allowed; nothing needs pre-zeroing) ----
__device__ __align__(16) float g_tm[BB * NN];
__device__ float g_rsum[BB * RR];
__device__ float g_rcnt[BB * RR];
__device__ int   g_nan_cnt[NCTA];
__device__ int   g_nan_list[NCTA * (GPC * 4)];
__device__ unsigned g_bar_cnt = 0;
__device__ unsigned g_bar_gen = 0;

// ---------------- grid barrier (all NCTA CTAs resident: single wave) --------
__device__ __forceinline__ void grid_sync() {
    __syncthreads();
    if (threadIdx.x == 0) {
        __threadfence();                               // publish my writes
        unsigned gen = *(volatile unsigned*)&g_bar_gen;
        if (atomicAdd(&g_bar_cnt, 1u) == NCTA - 1) {
            g_bar_cnt = 0;
            __threadfence();
            atomicAdd(&g_bar_gen, 1u);                 // release
        } else {
            while (*(volatile unsigned*)&g_bar_gen == gen) { __nanosleep(64); }
        }
    }
    __syncthreads();
    __threadfence();                                   // gpu-scope ordering
}

__device__ __forceinline__ float warp_red(float v) {
#pragma unroll
    for (int o = 16; o; o >>= 1) v += __shfl_xor_sync(0xffffffffu, v, o);
    return v;
}

// ---------------------------------------------------------------------------
__global__ void __launch_bounds__(THREADS, 1)
k_all(const float* __restrict__ seq, const int* __restrict__ cid32,
      float* __restrict__ out) {
    const int tid = threadIdx.x;
    const int bx  = blockIdx.x;           // n-tile
    const int b   = blockIdx.y;
    const int cta = b * GX + bx;

    // ===================== Phase 1: temporal nanmean ======================
    __shared__ int s_nan_base;
    if (tid == 0) s_nan_base = 0;
    __syncthreads();

    const bool act = tid < GPC;
    const int  g   = bx * GPC + tid;      // global triple index in [0,2500)
    const float4* rowp = reinterpret_cast<const float4*>(seq)
                         + (size_t)b * TT * ROW4 + (size_t)g * 3;

    float s0 = 0.f, s1 = 0.f, s2 = 0.f, s3 = 0.f;
    float c0 = 0.f, c1 = 0.f, c2 = 0.f, c3 = 0.f;
    if (act) {
#pragma unroll 6
        for (int t = 0; t < TT; t++) {
            const float4* p = rowp + (size_t)t * ROW4;
            float4 v0 = p[0], v1 = p[1], v2 = p[2];
            float f0 = v0.x, f1 = v0.w, f2 = v1.z, f3 = v2.y;  // channel-0 lanes
            if (f0 == f0) { s0 += f0; c0 += 1.f; }
            if (f1 == f1) { s1 += f1; c1 += 1.f; }
            if (f2 == f2) { s2 += f2; c2 += 1.f; }
            if (f3 == f3) { s3 += f3; c3 += 1.f; }
        }
    }

    if (act) {
        float4 tm = make_float4(s0 / c0, s1 / c1, s2 / c2, s3 / c3); // 0/0 -> NaN
        // out_pred [B,HH,NN] tiled copies (float4 slot g within 2500-wide rows)
        float4* op = reinterpret_cast<float4*>(out) + (size_t)b * HH * (NN / 4) + g;
#pragma unroll
        for (int h = 0; h < HH; h++) op[(size_t)h * (NN / 4)] = tm;
        reinterpret_cast<float4*>(g_tm)[b * (NN / 4) + g] = tm;

        // record all-NaN nodes (expected: none)
        int nanmask = (c0 == 0.f) | ((c1 == 0.f) << 1) | ((c2 == 0.f) << 2) | ((c3 == 0.f) << 3);
        if (nanmask) {
            int cnt = __popc(nanmask);
            int base = atomicAdd(&s_nan_base, cnt);
#pragma unroll
            for (int j = 0; j < 4; j++)
                if (nanmask & (1 << j))
                    g_nan_list[cta * (GPC * 4) + base++] = g * 4 + j;
        }
    }
    __syncthreads();
    if (tid == 0) g_nan_cnt[cta] = s_nan_base;

    // ---- detect cluster_id dtype (int64-LE => odd int32 words all zero) ----
    __shared__ int s_is64;
    int z = (cid32[2 * tid + 1] == 0);             // indices <=1279, in-bounds
    int tot = __syncthreads_count(z);
    if (tid == 0) s_is64 = (tot > THREADS / 2);
    __syncthreads();
    const bool is64 = s_is64;

    grid_sync();   // g_tm complete everywhere

    // ============ Phase 2: per-(b,region) sums via predicate scan ==========
    __shared__ float sm_s[20], sm_c[20];
    const int wid  = tid >> 5;
    const int lane = tid & 31;
#pragma unroll
    for (int q = 0; q < PAIRS_PER_CTA; q++) {
        const int p  = cta * PAIRS_PER_CTA + q;    // pair id in [0,640)
        const int pb = p / RR;
        const int pr = p % RR;
        float s = 0.f, c = 0.f;
        for (int n = tid; n < NN; n += THREADS) {
            float v = g_tm[pb * NN + n];
            int   r = is64 ? cid32[2 * n] : cid32[n];
            if (r == pr && v == v) { s += v; c += 1.f; }
        }
        s = warp_red(s); c = warp_red(c);
        if (lane == 0) { sm_s[wid] = s; sm_c[wid] = c; }
        __syncthreads();
        if (wid == 0) {
            float ws = (lane < 20) ? sm_s[lane] : 0.f;
            float wc = (lane < 20) ? sm_c[lane] : 0.f;
            ws = warp_red(ws); wc = warp_red(wc);
            if (lane == 0) { g_rsum[p] = ws; g_rcnt[p] = wc; }
        }
        __syncthreads();
    }

    grid_sync();   // all 640 pair sums visible

    // ============ Phase 3: CTA 0 finalizes (regional, g1/g2, NaN fix) ======
    if (cta == 0) {
        __shared__ float s_gs, s_gc, s_2s, s_2c;
        if (tid == 0) { s_gs = 0.f; s_gc = 0.f; s_2s = 0.f; s_2c = 0.f; }
        __syncthreads();

        const float rs = g_rsum[tid];              // tid == pair id (640)
        const float rc = g_rcnt[tid];
        atomicAdd(&s_gs, rs);
        atomicAdd(&s_gc, rc);
        const float reg = rs / rc;                 // NaN if region empty
        if (rc > 0.f) { atomicAdd(&s_2s, reg); atomicAdd(&s_2c, 1.f); }
        __syncthreads();

        const float g1 = s_gs / s_gc;
        const float g2 = s_2s / s_2c;
        const float val = (rc > 0.f) ? reg : g2;

        const int pb = tid / RR;
        const int pr = tid % RR;
        float* oreg = out + (size_t)BB * HH * NN;
#pragma unroll
        for (int h = 0; h < HH; h++)
            oreg[(pb * HH + h) * RR + pr] = val;

        // NaN backfill of out_pred (expected zero iterations)
        if (tid < NCTA) {
            const int cnt = g_nan_cnt[tid];
            const int nb  = tid / GX;              // that CTA's b
            for (int i = 0; i < cnt; i++) {
                const int n = g_nan_list[tid * (GPC * 4) + i];
#pragma unroll
                for (int h = 0; h < HH; h++)
                    out[((size_t)nb * HH + h) * NN + n] = g1;
            }
        }
    }
}

// ---------------------------------------------------------------------------
extern "C" void kernel_launch(void* const* d_in, const int* in_sizes, int n_in,
                              void* d_out, int out_size) {
    const float* seq   = (const float*)d_in[0];
    const int*   cid32 = (const int*)d_in[1];
    float*       out   = (float*)d_out;

    dim3 grid(GX, BB);
    k_all<<<grid, THREADS>>>(seq, cid32, out);
}

// round 7
// speedup vs baseline: 1.0004x; 1.0004x over previous
#include <cuda_runtime.h>
#include <cstdint>

#define BB 32
#define TT 36
#define NN 10000
#define HH 10
#define RR 20

#define THREADS 256
#define GXB 10                  // blocks per batch row: 10*256 >= 2500 triples
#define NCTA (GXB * BB)         // 320
#define TRIPLES 2500            // NN/4 float4-triples (4 nodes each)
#define ROW4 7500               // NN*3/4 float4 per (b,t) row
#define UB 6                    // timesteps batched -> 18 LDG.128 in flight
#define NANCAP 4096

// ---- device scratch (zero-initialized at load; finalizer re-zeros) ----
__device__ float    g_rsum[BB * RR];
__device__ float    g_rcnt[BB * RR];
__device__ unsigned g_done = 0;
__device__ int      g_nan_n = 0;
__device__ int      g_nan_list[NANCAP];

// ---------------------------------------------------------------------------
__global__ void __launch_bounds__(THREADS, 2)
k_all(const float* __restrict__ seq, const int* __restrict__ cid32,
      float* __restrict__ out) {
    const int tid = threadIdx.x;
    const int b   = blockIdx.y;
    const int g   = blockIdx.x * THREADS + tid;    // triple index
    const bool act = g < TRIPLES;

    __shared__ float srs[RR], src[RR];
    __shared__ int   s_is64;
    if (tid < RR) { srs[tid] = 0.f; src[tid] = 0.f; }
    if (tid < 32) {
        // int64-LE cluster_id => odd int32 words (upper halves) are all zero
        unsigned m = __ballot_sync(0xffffffffu, cid32[2 * tid + 1] == 0);
        if (tid == 0) s_is64 = (__popc(m) > 16);
    }
    __syncthreads();

    // ================= Phase 1: temporal nanmean (deep-MLP stream) =========
    float s0 = 0.f, s1 = 0.f, s2 = 0.f, s3 = 0.f;
    float c0 = 0.f, c1 = 0.f, c2 = 0.f, c3 = 0.f;
    if (act) {
        const float4* base = reinterpret_cast<const float4*>(seq)
                             + (size_t)b * TT * ROW4 + (size_t)g * 3;
#pragma unroll
        for (int tb = 0; tb < TT / UB; tb++) {
            float4 v[UB][3];                        // 18 independent LDG.128
#pragma unroll
            for (int u = 0; u < UB; u++) {
                const float4* p = base + (size_t)(tb * UB + u) * ROW4;
                v[u][0] = p[0]; v[u][1] = p[1]; v[u][2] = p[2];
            }
#pragma unroll
            for (int u = 0; u < UB; u++) {
                float f0 = v[u][0].x, f1 = v[u][0].w;   // channel-0 lanes
                float f2 = v[u][1].z, f3 = v[u][2].y;
                if (f0 == f0) { s0 += f0; c0 += 1.f; }
                if (f1 == f1) { s1 += f1; c1 += 1.f; }
                if (f2 == f2) { s2 += f2; c2 += 1.f; }
                if (f3 == f3) { s3 += f3; c3 += 1.f; }
            }
        }

        float4 tm = make_float4(s0 / c0, s1 / c1, s2 / c2, s3 / c3); // 0/0->NaN
        float4* op = reinterpret_cast<float4*>(out) + (size_t)b * HH * TRIPLES + g;
#pragma unroll
        for (int h = 0; h < HH; h++) op[(size_t)h * TRIPLES] = tm;

        // region accumulation (shared atomics)
        int r0, r1, r2, r3;
        if (s_is64) {
            int4 a = *reinterpret_cast<const int4*>(cid32 + g * 8);
            int4 q = *reinterpret_cast<const int4*>(cid32 + g * 8 + 4);
            r0 = a.x; r1 = a.z; r2 = q.x; r3 = q.z;
        } else {
            int4 a = *reinterpret_cast<const int4*>(cid32 + g * 4);
            r0 = a.x; r1 = a.y; r2 = a.z; r3 = a.w;
        }
        float tv[4] = { tm.x, tm.y, tm.z, tm.w };
        float cv[4] = { c0, c1, c2, c3 };
        int   rv[4] = { r0, r1, r2, r3 };
#pragma unroll
        for (int j = 0; j < 4; j++) {
            if (cv[j] > 0.f) {
                atomicAdd(&srs[rv[j]], tv[j]);
                atomicAdd(&src[rv[j]], 1.f);
            } else {                                 // all-NaN node (p ~ 1e-47)
                int slot = atomicAdd(&g_nan_n, 1);
                if (slot < NANCAP) g_nan_list[slot] = b * NN + g * 4 + j;
            }
        }
    }
    __syncthreads();
    if (tid < RR && src[tid] != 0.f) {
        atomicAdd(&g_rsum[b * RR + tid], srs[tid]);
        atomicAdd(&g_rcnt[b * RR + tid], src[tid]);
    }

    // ================= completion: last block finalizes ====================
    __shared__ bool s_last;
    __syncthreads();
    if (tid == 0) {
        __threadfence();
        s_last = (atomicAdd(&g_done, 1u) == NCTA - 1);
    }
    __syncthreads();
    if (!s_last) return;

    __threadfence();                                 // acquire others' writes

    __shared__ float s_gs, s_gc, s_2s, s_2c;
    if (tid == 0) { s_gs = 0.f; s_gc = 0.f; s_2s = 0.f; s_2c = 0.f; }
    __syncthreads();

    float rs[3], rc[3];                              // 640 pairs / 256 threads
#pragma unroll
    for (int q = 0; q < 3; q++) {
        int p = tid + q * THREADS;
        if (p < BB * RR) {
            rs[q] = g_rsum[p]; rc[q] = g_rcnt[p];
            atomicAdd(&s_gs, rs[q]);
            atomicAdd(&s_gc, rc[q]);
            if (rc[q] > 0.f) { atomicAdd(&s_2s, rs[q] / rc[q]); atomicAdd(&s_2c, 1.f); }
        }
    }
    __syncthreads();
    const float g1 = s_gs / s_gc;                    // global nanmean(pred)
    const float g2 = s_2s / s_2c;                    // global nanmean(regional)

    float* oreg = out + (size_t)BB * HH * NN;
#pragma unroll
    for (int q = 0; q < 3; q++) {
        int p = tid + q * THREADS;
        if (p < BB * RR) {
            float val = (rc[q] > 0.f) ? rs[q] / rc[q] : g2;
            int pb = p / RR, pr = p % RR;
#pragma unroll
            for (int h = 0; h < HH; h++)
                oreg[(pb * HH + h) * RR + pr] = val;
        }
    }

    // NaN backfill of out_pred (expected zero entries)
    int nn = min(g_nan_n, NANCAP);
    for (int i = tid; i < nn; i += THREADS) {
        int idx = g_nan_list[i];
        int nb = idx / NN, n = idx % NN;
#pragma unroll
        for (int h = 0; h < HH; h++)
            out[((size_t)nb * HH + h) * NN + n] = g1;
    }

    // reset scratch for next graph replay
    __syncthreads();
    for (int p = tid; p < BB * RR; p += THREADS) { g_rsum[p] = 0.f; g_rcnt[p] = 0.f; }
    if (tid == 0) { g_done = 0; g_nan_n = 0; }
}

// ---------------------------------------------------------------------------
extern "C" void kernel_launch(void* const* d_in, const int* in_sizes, int n_in,
                              void* d_out, int out_size) {
    const float* seq   = (const float*)d_in[0];
    const int*   cid32 = (const int*)d_in[1];
    float*       out   = (float*)d_out;

    dim3 grid(GXB, BB);
    k_all<<<grid, THREADS>>>(seq, cid32, out);
}

// round 8
// speedup vs baseline: 1.0174x; 1.0170x over previous
#include <cuda_runtime.h>
#include <cstdint>

#define BB 32
#define TT 36
#define NN 10000
#define FF 3
#define HH 10
#define RR 20

#define THREADS 256
#define GXB 40                  // ceil(NN/256)
#define NCTA (GXB * BB)         // 1280
#define NANCAP 4096

// ---- device scratch (zero-initialized at load; finalizer re-zeros) ----
__device__ float    g_rsum[BB * RR];
__device__ float    g_rcnt[BB * RR];
__device__ unsigned g_done = 0;
__device__ int      g_nan_n = 0;
__device__ int      g_nan_list[NANCAP];

// ---------------------------------------------------------------------------
// Single fused kernel. grid = (40, 32), block = 256. One thread per (b, n).
// ---------------------------------------------------------------------------
__global__ void k_main(const float* __restrict__ seq,
                       const int* __restrict__ cid32,
                       float* __restrict__ out) {
    const int tid = threadIdx.x;
    const int b   = blockIdx.y;
    const int n   = blockIdx.x * THREADS + tid;

    __shared__ float srs[RR], src[RR];
    __shared__ int   s_is64;
    if (tid < RR) { srs[tid] = 0.f; src[tid] = 0.f; }
    if (tid < 32) {
        // int64-LE cluster_id => odd int32 words (upper halves) all zero
        unsigned m = __ballot_sync(0xffffffffu, cid32[2 * tid + 1] == 0);
        if (tid == 0) s_is64 = (__popc(m) > 16);
    }
    __syncthreads();

    // ============ Phase 1: temporal nanmean, R1-style scalar stream ========
    if (n < NN) {
        const float* p = seq + ((size_t)b * TT * NN + (size_t)n) * FF;
        float sa = 0.f, ca = 0.f, sb = 0.f, cb = 0.f;   // split dep chains
#pragma unroll
        for (int t = 0; t < TT; t += 2) {
            float v0 = p[(size_t)t * NN * FF];
            float v1 = p[(size_t)(t + 1) * NN * FF];
            if (v0 == v0) { sa += v0; ca += 1.f; }
            if (v1 == v1) { sb += v1; cb += 1.f; }
        }
        const float c  = ca + cb;
        const float tm = (sa + sb) / c;                 // 0/0 -> NaN
        // fused out_pred [B,HH,NN]: coalesced streaming stores
        float* op = out + (size_t)b * HH * NN + n;
#pragma unroll
        for (int h = 0; h < HH; h++) __stcs(op + (size_t)h * NN, tm);

        if (c > 0.f) {
            const int r = s_is64 ? cid32[2 * n] : cid32[n];
            atomicAdd(&srs[r], tm);
            atomicAdd(&src[r], 1.f);
        } else {                                        // all-NaN node (p~0)
            int slot = atomicAdd(&g_nan_n, 1);
            if (slot < NANCAP) g_nan_list[slot] = b * NN + n;
        }
    }
    __syncthreads();
    if (tid < RR && src[tid] != 0.f) {
        atomicAdd(&g_rsum[b * RR + tid], srs[tid]);
        atomicAdd(&g_rcnt[b * RR + tid], src[tid]);
    }

    // ================= completion: last block finalizes ====================
    __shared__ bool s_last;
    __syncthreads();
    if (tid == 0) {
        __threadfence();
        s_last = (atomicAdd(&g_done, 1u) == NCTA - 1);
    }
    __syncthreads();
    if (!s_last) return;

    __threadfence();                                    // acquire others' writes

    __shared__ float s_gs, s_gc, s_2s, s_2c;
    if (tid == 0) { s_gs = 0.f; s_gc = 0.f; s_2s = 0.f; s_2c = 0.f; }
    __syncthreads();

    float rs[3], rc[3];                                 // 640 pairs / 256 thr
#pragma unroll
    for (int q = 0; q < 3; q++) {
        int pidx = tid + q * THREADS;
        if (pidx < BB * RR) {
            rs[q] = g_rsum[pidx]; rc[q] = g_rcnt[pidx];
            atomicAdd(&s_gs, rs[q]);
            atomicAdd(&s_gc, rc[q]);
            if (rc[q] > 0.f) { atomicAdd(&s_2s, rs[q] / rc[q]); atomicAdd(&s_2c, 1.f); }
        }
    }
    __syncthreads();
    const float g1 = s_gs / s_gc;                       // nanmean(pred)
    const float g2 = s_2s / s_2c;                       // nanmean(regional)

    float* oreg = out + (size_t)BB * HH * NN;
#pragma unroll
    for (int q = 0; q < 3; q++) {
        int pidx = tid + q * THREADS;
        if (pidx < BB * RR) {
            float val = (rc[q] > 0.f) ? rs[q] / rc[q] : g2;
            int pb = pidx / RR, pr = pidx % RR;
#pragma unroll
            for (int h = 0; h < HH; h++)
                oreg[(pb * HH + h) * RR + pr] = val;
        }
    }

    // NaN backfill of out_pred (expected zero entries)
    int nn = min(g_nan_n, NANCAP);
    for (int i = tid; i < nn; i += THREADS) {
        int idx = g_nan_list[i];
        int nb = idx / NN, nd = idx % NN;
#pragma unroll
        for (int h = 0; h < HH; h++)
            out[((size_t)nb * HH + h) * NN + nd] = g1;
    }

    // reset scratch for next graph replay
    __syncthreads();
    for (int pidx = tid; pidx < BB * RR; pidx += THREADS) {
        g_rsum[pidx] = 0.f; g_rcnt[pidx] = 0.f;
    }
    if (tid == 0) { g_done = 0; g_nan_n = 0; }
}

// ---------------------------------------------------------------------------
extern "C" void kernel_launch(void* const* d_in, const int* in_sizes, int n_in,
                              void* d_out, int out_size) {
    const float* seq   = (const float*)d_in[0];
    const int*   cid32 = (const int*)d_in[1];
    float*       out   = (float*)d_out;

    dim3 grid(GXB, BB);
    k_main<<<grid, THREADS>>>(seq, cid32, out);
}